// round 4
// baseline (speedup 1.0000x reference)
#include <cuda_runtime.h>
#include <math.h>

#define NB 32768
#define ND 1024
#define NC 256
#define PAD 1024
#define NSPLIT 4
#define LOSS_WEIGHT 0.0005
#define EPSN 1e-12f

// ---- static scratch (zero-initialized at module load) ----
__device__ int    g_cnt[NC];                    // invariant: 0 at kernel_launch entry
__device__ int    g_cidx[NC * PAD];             // padded per-class member lists (unordered)
__device__ int    g_sorted[NC * PAD];           // ascending-index member lists
__device__ float  g_part[NSPLIT * NC * ND];     // per-(split,class) partial sums
__device__ float  g_pnf2[NSPLIT * NC];          // per-(split,class) partial sum ||f||^2
__device__ float  g_sums[NC * ND];              // S_c
__device__ float  g_s2[NC];                     // ||S_c||^2
__device__ double g_accum;                      // invariant: 0 at entry

// ---- K1: block-aggregated scatter into padded class slots ----
__global__ __launch_bounds__(1024) void k_scatter(const int* __restrict__ lab) {
    __shared__ int scnt[NC];
    __shared__ int sbase[NC];
    int t = threadIdx.x;
    if (t < NC) scnt[t] = 0;
    __syncthreads();
    int row = blockIdx.x * 1024 + t;
    int c = lab[row];
    int myrank = atomicAdd(&scnt[c], 1);
    __syncthreads();
    if (t < NC && scnt[t] > 0) sbase[t] = atomicAdd(&g_cnt[t], scnt[t]);
    __syncthreads();
    int pos = sbase[c] + myrank;
    if (pos < PAD) g_cidx[c * PAD + pos] = row;
}

// ---- K2: fused norms + partial class sums. block = (class, quarter) ----
// 8 warps; warp w handles chunk-local members w, w+8, ... Lane owns 32 dims.
__global__ __launch_bounds__(256) void k_fused(const float* __restrict__ x) {
    int c = blockIdx.x >> 2, q = blockIdx.x & 3;
    int n = g_cnt[c];
    if (n > PAD) n = PAD;
    int chunk = (n + NSPLIT - 1) >> 2;
    int j0 = q * chunk;
    int j1 = j0 + chunk; if (j1 > n) j1 = n;
    int cnt = j1 - j0; if (cnt < 0) cnt = 0;

    __shared__ int    sidx[288];
    __shared__ float  smacc[8][ND];     // 32KB cross-warp combine
    __shared__ float  snf2[8];
    int t = threadIdx.x, lane = t & 31, w = t >> 5;

    if (t < cnt) sidx[t] = g_cidx[c * PAD + j0 + t];
    __syncthreads();

    const float4* xb = (const float4*)x;
    float4 acc[8];
#pragma unroll
    for (int k = 0; k < 8; k++) acc[k] = make_float4(0.f, 0.f, 0.f, 0.f);
    float nf2 = 0.f;

    float4 buf[2][8];
    if (w < cnt) {
        size_t base = (size_t)sidx[w] * 256 + lane;
#pragma unroll
        for (int k = 0; k < 8; k++) buf[0][k] = xb[base + k * 32];
    }
    int b = 0;
    for (int j = w; j < cnt; j += 8) {
        int jn = j + 8;
        if (jn < cnt) {
            size_t base2 = (size_t)sidx[jn] * 256 + lane;
#pragma unroll
            for (int k = 0; k < 8; k++) buf[b ^ 1][k] = xb[base2 + k * 32];
        }
        float ss = 0.f;
#pragma unroll
        for (int k = 0; k < 8; k++) {
            float4 v = buf[b][k];
            ss += v.x * v.x + v.y * v.y + v.z * v.z + v.w * v.w;
        }
#pragma unroll
        for (int o = 16; o; o >>= 1) ss += __shfl_xor_sync(0xFFFFFFFFu, ss, o);
        float inv = 1.0f / fmaxf(sqrtf(ss), EPSN);
#pragma unroll
        for (int k = 0; k < 8; k++) {
            float4 v = buf[b][k];
            acc[k].x += v.x * inv; acc[k].y += v.y * inv;
            acc[k].z += v.z * inv; acc[k].w += v.w * inv;
        }
        nf2 += ss * inv * inv;
        b ^= 1;
    }

#pragma unroll
    for (int k = 0; k < 8; k++)
        ((float4*)smacc[w])[k * 32 + lane] = acc[k];
    if (lane == 0) snf2[w] = nf2;
    __syncthreads();

    // combine 8 warps; thread t owns dims 4t..4t+3
    float4 s = ((float4*)smacc[0])[t];
#pragma unroll
    for (int u = 1; u < 8; u++) {
        float4 p = ((float4*)smacc[u])[t];
        s.x += p.x; s.y += p.y; s.z += p.z; s.w += p.w;
    }
    ((float4*)(g_part + (size_t)(q * NC + c) * ND))[t] = s;
    if (t == 0) {
        float nft = 0.f;
#pragma unroll
        for (int u = 0; u < 8; u++) nft += snf2[u];
        g_pnf2[q * NC + c] = nft;
    }
}

// ---- K3: combine partials -> S_c, ||S_c||^2, base contribution; sort members ----
__global__ __launch_bounds__(256) void k_comb() {
    int c = blockIdx.x, t = threadIdx.x;
    int n = g_cnt[c];
    if (n > PAD) n = PAD;

    float4 s = make_float4(0.f, 0.f, 0.f, 0.f);
#pragma unroll
    for (int q = 0; q < NSPLIT; q++) {
        float4 p = ((const float4*)(g_part + (size_t)(q * NC + c) * ND))[t];
        s.x += p.x; s.y += p.y; s.z += p.z; s.w += p.w;
    }
    ((float4*)(g_sums + (size_t)c * ND))[t] = s;

    float sq = s.x * s.x + s.y * s.y + s.z * s.z + s.w * s.w;
#pragma unroll
    for (int o = 16; o; o >>= 1) sq += __shfl_xor_sync(0xFFFFFFFFu, sq, o);
    __shared__ float sred[8];
    int lane = t & 31, w = t >> 5;
    if (lane == 0) sred[w] = sq;

    // sort member list by ascending global index (rank via count-smaller)
    __shared__ int sm_m[PAD];
    for (int j = t; j < n; j += 256) sm_m[j] = g_cidx[c * PAD + j];
    __syncthreads();
    for (int j = t; j < n; j += 256) {
        int mj = sm_m[j];
        int rank = 0;
        for (int u = 0; u < n; u++) rank += (sm_m[u] < mj);
        g_sorted[c * PAD + rank] = mj;
    }

    if (t == 0) {
        float s2 = 0.f;
#pragma unroll
        for (int u = 0; u < 8; u++) s2 += sred[u];
        g_s2[c] = s2;
        double nf2 = 0.0;
#pragma unroll
        for (int q = 0; q < NSPLIT; q++) nf2 += (double)g_pnf2[q * NC + c];
        if (n > 1) {
            double base = (nf2 - (double)s2 / (double)n) / (double)ND;
            atomicAdd(&g_accum, base);
        }
    }
}

// ---- K4: warp-per-sample exclusion correction (only i < n_c fire) ----
__global__ __launch_bounds__(256) void k_corr(const float* __restrict__ x,
                                              const int* __restrict__ lab) {
    int i = blockIdx.x * 8 + (threadIdx.x >> 5);   // global sample index, 0..511
    int lane = threadIdx.x & 31;
    int c = lab[i];
    int n = g_cnt[c];
    if (i >= n || n <= 1) return;
    int k = g_sorted[c * PAD + i];

    const float4* xi = (const float4*)x + (size_t)i * 256;
    const float4* xk = (const float4*)x + (size_t)k * 256;
    const float4* sc = (const float4*)g_sums + (size_t)c * 256;
    float a_ii = 0.f, a_ik = 0.f, a_kk = 0.f, a_is = 0.f, a_ks = 0.f;
#pragma unroll
    for (int q = 0; q < 8; q++) {
        float4 vi = xi[q * 32 + lane];
        float4 vk = xk[q * 32 + lane];
        float4 vs = sc[q * 32 + lane];
        a_ii += vi.x * vi.x + vi.y * vi.y + vi.z * vi.z + vi.w * vi.w;
        a_ik += vi.x * vk.x + vi.y * vk.y + vi.z * vk.z + vi.w * vk.w;
        a_kk += vk.x * vk.x + vk.y * vk.y + vk.z * vk.z + vk.w * vk.w;
        a_is += vi.x * vs.x + vi.y * vs.y + vi.z * vs.z + vi.w * vs.w;
        a_ks += vk.x * vs.x + vk.y * vs.y + vk.z * vs.z + vk.w * vs.w;
    }
#pragma unroll
    for (int o = 16; o; o >>= 1) {
        a_ii += __shfl_xor_sync(0xFFFFFFFFu, a_ii, o);
        a_ik += __shfl_xor_sync(0xFFFFFFFFu, a_ik, o);
        a_kk += __shfl_xor_sync(0xFFFFFFFFu, a_kk, o);
        a_is += __shfl_xor_sync(0xFFFFFFFFu, a_is, o);
        a_ks += __shfl_xor_sync(0xFFFFFFFFu, a_ks, o);
    }
    if (lane == 0) {
        float inv_i = 1.0f / fmaxf(sqrtf(a_ii), EPSN);
        float inv_k = 1.0f / fmaxf(sqrtf(a_kk), EPSN);
        float s2 = g_s2[c];
        double nf2_i = (double)a_ii * inv_i * inv_i;
        double fiS   = (double)a_is * inv_i;
        double fifk  = (double)a_ik * inv_i * inv_k;
        double fkS   = (double)a_ks * inv_k;
        double nf2_k = (double)a_kk * inv_k * inv_k;
        double dn = (double)n;
        double base = (nf2_i - 2.0 * fiS / dn + (double)s2 / (dn * dn)) / (double)ND;
        double m = dn - 1.0;
        double fic  = (fiS - fifk) / m;
        double c2   = ((double)s2 - 2.0 * fkS + nf2_k) / (m * m);
        double excl = (nf2_i - 2.0 * fic + c2) / (double)ND;
        atomicAdd(&g_accum, excl - base);
    }
}

// ---- K5: finalize + restore zero-invariants for next call ----
__global__ void k_final(float* out) {
    int t = threadIdx.x;
    if (t == 0) {
        out[0] = (float)(LOSS_WEIGHT * g_accum / (double)NB);
        g_accum = 0.0;
    }
    if (t < NC) g_cnt[t] = 0;
}

extern "C" void kernel_launch(void* const* d_in, const int* in_sizes, int n_in,
                              void* d_out, int out_size) {
    const float* x   = (const float*)d_in[0];
    const int*   lab = (const int*)d_in[1];
    float* out = (float*)d_out;
    (void)in_sizes; (void)n_in; (void)out_size;

    k_scatter<<<NB / 1024, 1024>>>(lab);
    k_fused<<<NC * NSPLIT, 256>>>(x);
    k_comb<<<NC, 256>>>();
    k_corr<<<64, 256>>>(x, lab);
    k_final<<<1, 256>>>(out);
}

// round 5
// speedup vs baseline: 1.0355x; 1.0355x over previous
#include <cuda_runtime.h>
#include <math.h>

#define NB 32768
#define ND 1024
#define NC 256
#define PAD 1024
#define LOSS_WEIGHT 0.0005
#define EPSN 1e-12f

// ---- static scratch (zero-initialized at module load; invariants restored by k_final) ----
__device__ int    g_cnt[NC];              // 0 at entry
__device__ int    g_cidx[NC * PAD];       // padded per-class member lists (unordered)
__device__ int    g_sorted[NC * PAD];     // ascending-index member lists
__device__ float  g_part[2 * NC * ND];    // per-(half,class) partial sums
__device__ float  g_pnf2[2 * NC];
__device__ float  g_sums[NC * ND];        // S_c
__device__ float  g_s2[NC];               // ||S_c||^2
__device__ double g_accum;                // 0 at entry

// ---- K1: block-aggregated scatter into padded class slots ----
__global__ __launch_bounds__(1024) void k_scatter(const int* __restrict__ lab) {
    __shared__ int scnt[NC];
    __shared__ int sbase[NC];
    int t = threadIdx.x;
    if (t < NC) scnt[t] = 0;
    __syncthreads();
    int row = blockIdx.x * 1024 + t;
    int c = lab[row];
    int myrank = atomicAdd(&scnt[c], 1);
    __syncthreads();
    if (t < NC && scnt[t] > 0) sbase[t] = atomicAdd(&g_cnt[t], scnt[t]);
    __syncthreads();
    int pos = sbase[c] + myrank;
    if (pos < PAD) g_cidx[c * PAD + pos] = row;
}

// ---- K2: fused norms + partial class sums. block = (class, half), 4 warps ----
// Warp w handles chunk-local members w, w+4, ... Lane owns 32 dims (8 x float4).
__global__ __launch_bounds__(128, 4) void k_fused(const float* __restrict__ x) {
    int c = blockIdx.x >> 1, h = blockIdx.x & 1;
    int n = g_cnt[c];
    if (n > PAD) n = PAD;
    int half = (n + 1) >> 1;
    int j0 = h * half;
    int j1 = j0 + half; if (j1 > n) j1 = n;
    int cnt = j1 - j0; if (cnt < 0) cnt = 0;

    __shared__ int   sidx[512];
    __shared__ float smacc[4][ND];    // 16KB cross-warp combine
    __shared__ float snf2[4];
    int t = threadIdx.x, lane = t & 31, w = t >> 5;

    for (int j = t; j < cnt; j += 128) sidx[j] = g_cidx[c * PAD + j0 + j];
    __syncthreads();

    const float4* xb = (const float4*)x;
    float4 acc[8];
#pragma unroll
    for (int k = 0; k < 8; k++) acc[k] = make_float4(0.f, 0.f, 0.f, 0.f);
    float nf2 = 0.f;

    float4 buf[2][8];
    if (w < cnt) {
        size_t base = (size_t)sidx[w] * 256 + lane;
#pragma unroll
        for (int k = 0; k < 8; k++) buf[0][k] = xb[base + k * 32];
    }
    int b = 0;
    for (int j = w; j < cnt; j += 4) {
        int jn = j + 4;
        if (jn < cnt) {
            size_t base2 = (size_t)sidx[jn] * 256 + lane;
#pragma unroll
            for (int k = 0; k < 8; k++) buf[b ^ 1][k] = xb[base2 + k * 32];
        }
        float ss = 0.f;
#pragma unroll
        for (int k = 0; k < 8; k++) {
            float4 v = buf[b][k];
            ss += v.x * v.x + v.y * v.y + v.z * v.z + v.w * v.w;
        }
#pragma unroll
        for (int o = 16; o; o >>= 1) ss += __shfl_xor_sync(0xFFFFFFFFu, ss, o);
        float inv = 1.0f / fmaxf(sqrtf(ss), EPSN);
#pragma unroll
        for (int k = 0; k < 8; k++) {
            float4 v = buf[b][k];
            acc[k].x += v.x * inv; acc[k].y += v.y * inv;
            acc[k].z += v.z * inv; acc[k].w += v.w * inv;
        }
        nf2 += ss * inv * inv;
        b ^= 1;
    }

#pragma unroll
    for (int k = 0; k < 8; k++)
        ((float4*)smacc[w])[k * 32 + lane] = acc[k];
    if (lane == 0) snf2[w] = nf2;
    __syncthreads();

    // combine 4 warps; thread t owns float4 chunks t and t+128
    float* dst = g_part + (size_t)(h * NC + c) * ND;
#pragma unroll
    for (int r = 0; r < 2; r++) {
        int idx = t + r * 128;
        float4 s = ((float4*)smacc[0])[idx];
#pragma unroll
        for (int u = 1; u < 4; u++) {
            float4 p = ((float4*)smacc[u])[idx];
            s.x += p.x; s.y += p.y; s.z += p.z; s.w += p.w;
        }
        ((float4*)dst)[idx] = s;
    }
    if (t == 0) {
        float nft = 0.f;
#pragma unroll
        for (int u = 0; u < 4; u++) nft += snf2[u];
        g_pnf2[h * NC + c] = nft;
    }
}

// ---- K3: combine halves -> S_c, ||S_c||^2, base contribution; sort members ----
__global__ __launch_bounds__(256) void k_comb() {
    int c = blockIdx.x, t = threadIdx.x;
    int n = g_cnt[c];
    if (n > PAD) n = PAD;

    float4 p0 = ((const float4*)(g_part + (size_t)c * ND))[t];
    float4 p1 = ((const float4*)(g_part + (size_t)(NC + c) * ND))[t];
    float4 s = make_float4(p0.x + p1.x, p0.y + p1.y, p0.z + p1.z, p0.w + p1.w);
    ((float4*)(g_sums + (size_t)c * ND))[t] = s;

    float sq = s.x * s.x + s.y * s.y + s.z * s.z + s.w * s.w;
#pragma unroll
    for (int o = 16; o; o >>= 1) sq += __shfl_xor_sync(0xFFFFFFFFu, sq, o);
    __shared__ float sred[8];
    int lane = t & 31, w = t >> 5;
    if (lane == 0) sred[w] = sq;

    // sort member list by ascending global index (rank via count-smaller)
    __shared__ int sm_m[PAD];
    for (int j = t; j < n; j += 256) sm_m[j] = g_cidx[c * PAD + j];
    __syncthreads();
    for (int j = t; j < n; j += 256) {
        int mj = sm_m[j];
        int rank = 0;
        for (int u = 0; u < n; u++) rank += (sm_m[u] < mj);
        g_sorted[c * PAD + rank] = mj;
    }

    if (t == 0) {
        float s2 = 0.f;
#pragma unroll
        for (int u = 0; u < 8; u++) s2 += sred[u];
        g_s2[c] = s2;
        double nf2 = (double)g_pnf2[c] + (double)g_pnf2[NC + c];
        if (n > 1) {
            double base = (nf2 - (double)s2 / (double)n) / (double)ND;
            atomicAdd(&g_accum, base);
        }
    }
}

// ---- K4: warp-per-sample exclusion correction (only i < n_c fire) ----
__global__ __launch_bounds__(128) void k_corr(const float* __restrict__ x,
                                              const int* __restrict__ lab) {
    int i = blockIdx.x * 4 + (threadIdx.x >> 5);   // 0..511
    int lane = threadIdx.x & 31;
    int c = lab[i];
    int n = g_cnt[c];
    if (i >= n || n <= 1) return;
    int k = g_sorted[c * PAD + i];

    const float4* xi = (const float4*)x + (size_t)i * 256;
    const float4* xk = (const float4*)x + (size_t)k * 256;
    const float4* sc = (const float4*)g_sums + (size_t)c * 256;
    float a_ii = 0.f, a_ik = 0.f, a_kk = 0.f, a_is = 0.f, a_ks = 0.f;
#pragma unroll
    for (int q = 0; q < 8; q++) {
        float4 vi = xi[q * 32 + lane];
        float4 vk = xk[q * 32 + lane];
        float4 vs = sc[q * 32 + lane];
        a_ii += vi.x * vi.x + vi.y * vi.y + vi.z * vi.z + vi.w * vi.w;
        a_ik += vi.x * vk.x + vi.y * vk.y + vi.z * vk.z + vi.w * vk.w;
        a_kk += vk.x * vk.x + vk.y * vk.y + vk.z * vk.z + vk.w * vk.w;
        a_is += vi.x * vs.x + vi.y * vs.y + vi.z * vs.z + vi.w * vs.w;
        a_ks += vk.x * vs.x + vk.y * vs.y + vk.z * vs.z + vk.w * vs.w;
    }
#pragma unroll
    for (int o = 16; o; o >>= 1) {
        a_ii += __shfl_xor_sync(0xFFFFFFFFu, a_ii, o);
        a_ik += __shfl_xor_sync(0xFFFFFFFFu, a_ik, o);
        a_kk += __shfl_xor_sync(0xFFFFFFFFu, a_kk, o);
        a_is += __shfl_xor_sync(0xFFFFFFFFu, a_is, o);
        a_ks += __shfl_xor_sync(0xFFFFFFFFu, a_ks, o);
    }
    if (lane == 0) {
        float inv_i = 1.0f / fmaxf(sqrtf(a_ii), EPSN);
        float inv_k = 1.0f / fmaxf(sqrtf(a_kk), EPSN);
        float s2 = g_s2[c];
        double nf2_i = (double)a_ii * inv_i * inv_i;
        double fiS   = (double)a_is * inv_i;
        double fifk  = (double)a_ik * inv_i * inv_k;
        double fkS   = (double)a_ks * inv_k;
        double nf2_k = (double)a_kk * inv_k * inv_k;
        double dn = (double)n;
        double base = (nf2_i - 2.0 * fiS / dn + (double)s2 / (dn * dn)) / (double)ND;
        double m = dn - 1.0;
        double fic  = (fiS - fifk) / m;
        double c2   = ((double)s2 - 2.0 * fkS + nf2_k) / (m * m);
        double excl = (nf2_i - 2.0 * fic + c2) / (double)ND;
        atomicAdd(&g_accum, excl - base);
    }
}

// ---- K5: finalize + restore zero-invariants for next call ----
__global__ void k_final(float* out) {
    int t = threadIdx.x;
    if (t == 0) {
        out[0] = (float)(LOSS_WEIGHT * g_accum / (double)NB);
        g_accum = 0.0;
    }
    if (t < NC) g_cnt[t] = 0;
}

extern "C" void kernel_launch(void* const* d_in, const int* in_sizes, int n_in,
                              void* d_out, int out_size) {
    const float* x   = (const float*)d_in[0];
    const int*   lab = (const int*)d_in[1];
    float* out = (float*)d_out;
    (void)in_sizes; (void)n_in; (void)out_size;

    k_scatter<<<NB / 1024, 1024>>>(lab);
    k_fused<<<NC * 2, 128>>>(x);
    k_comb<<<NC, 256>>>();
    k_corr<<<128, 128>>>(x, lab);
    k_final<<<1, 256>>>(out);
}

// round 6
// speedup vs baseline: 1.0903x; 1.0529x over previous
#include <cuda_runtime.h>
#include <math.h>

#define NB 32768
#define ND 1024
#define NC 256
#define PAD 1024
#define CH 14                       // rows per warp-chunk
#define NCHUNK ((NB + CH - 1) / CH) // 2341
#define LOSS_WEIGHT 0.0005
#define EPSN 1e-12f

// ---- static scratch (zero at load; invariants restored by k_final/k_prefix) ----
__device__ int    g_cnt[NC];                 // 0 at entry
__device__ int    g_off[NC];
__device__ int    g_cursor[NC];
__device__ int    g_flat[NB];                // rows sorted (grouped) by class
__device__ int    g_sorted[NB];              // ascending-index member lists (flat, off-indexed)
__device__ float  g_part[(NCHUNK + 1) * 2 * ND];  // per-(chunk,segment) partial sums
__device__ float  g_pnf2[(NCHUNK + 1) * 2];
__device__ float  g_sums[NC * ND];           // S_c
__device__ float  g_s2[NC];                  // ||S_c||^2
__device__ double g_accum;                   // 0 at entry

// ---- K1: histogram ----
__global__ __launch_bounds__(1024) void k_hist(const int* __restrict__ lab) {
    __shared__ int scnt[NC];
    int t = threadIdx.x;
    if (t < NC) scnt[t] = 0;
    __syncthreads();
    atomicAdd(&scnt[lab[blockIdx.x * 1024 + t]], 1);
    __syncthreads();
    if (t < NC && scnt[t]) atomicAdd(&g_cnt[t], scnt[t]);
}

// ---- K2: exclusive prefix -> offsets; zero cursors ----
__global__ void k_prefix() {
    __shared__ int s[NC];
    int t = threadIdx.x;
    int v = g_cnt[t];
    s[t] = v;
    __syncthreads();
    int inc = v;
    for (int o = 1; o < NC; o <<= 1) {
        int add = (t >= o) ? s[t - o] : 0;
        __syncthreads();
        s[t] = inc = inc + add;
        __syncthreads();
    }
    g_off[t] = inc - v;
    g_cursor[t] = 0;
}

// ---- K3: block-aggregated scatter into flat class-sorted list ----
__global__ __launch_bounds__(1024) void k_scatter(const int* __restrict__ lab) {
    __shared__ int scnt[NC];
    __shared__ int sbase[NC];
    int t = threadIdx.x;
    if (t < NC) scnt[t] = 0;
    __syncthreads();
    int row = blockIdx.x * 1024 + t;
    int c = lab[row];
    int r = atomicAdd(&scnt[c], 1);
    __syncthreads();
    if (t < NC && scnt[t]) sbase[t] = atomicAdd(&g_cursor[t], scnt[t]);
    __syncthreads();
    g_flat[g_off[c] + sbase[c] + r] = row;
}

// ---- K4 (profiled slot): fused norms + segment partial sums, warp = 14 rows ----
__global__ __launch_bounds__(128, 4) void k_fused(const float* __restrict__ x,
                                                  const int* __restrict__ lab) {
    int g = blockIdx.x * 4 + (threadIdx.x >> 5);
    int lane = threadIdx.x & 31;
    int r0 = g * CH;
    if (r0 >= NB) return;
    int cnt = NB - r0; if (cnt > CH) cnt = CH;

    // fetch this chunk's row indices + classes (coalesced, then shfl-broadcast)
    int idx = 0, cl = -1;
    if (lane < cnt) { idx = g_flat[r0 + lane]; cl = lab[idx]; }

    const float4* xb = (const float4*)x;
    float4 acc[8];
#pragma unroll
    for (int k = 0; k < 8; k++) acc[k] = make_float4(0.f, 0.f, 0.f, 0.f);
    float nf2 = 0.f;
    int cur = __shfl_sync(0xFFFFFFFFu, cl, 0);
    int seg = 0;

    float4 buf[2][8];
    {
        int i0 = __shfl_sync(0xFFFFFFFFu, idx, 0);
        size_t base = (size_t)i0 * 256 + lane;
#pragma unroll
        for (int k = 0; k < 8; k++) buf[0][k] = xb[base + k * 32];
    }
    int b = 0;
    for (int j = 0; j < cnt; j++) {
        if (j + 1 < cnt) {
            int in = __shfl_sync(0xFFFFFFFFu, idx, j + 1);
            size_t base2 = (size_t)in * 256 + lane;
#pragma unroll
            for (int k = 0; k < 8; k++) buf[b ^ 1][k] = xb[base2 + k * 32];
        }
        float ss = 0.f;
#pragma unroll
        for (int k = 0; k < 8; k++) {
            float4 v = buf[b][k];
            ss += v.x * v.x + v.y * v.y + v.z * v.z + v.w * v.w;
        }
#pragma unroll
        for (int o = 16; o; o >>= 1) ss += __shfl_xor_sync(0xFFFFFFFFu, ss, o);
        float inv = 1.0f / fmaxf(sqrtf(ss), EPSN);

        int cj = __shfl_sync(0xFFFFFFFFu, cl, j);
        if (cj != cur) {                       // class boundary: flush segment 0
            float* dst = g_part + (size_t)(g * 2 + seg) * ND;
#pragma unroll
            for (int k = 0; k < 8; k++) ((float4*)dst)[k * 32 + lane] = acc[k];
            if (lane == 0) g_pnf2[g * 2 + seg] = nf2;
#pragma unroll
            for (int k = 0; k < 8; k++) acc[k] = make_float4(0.f, 0.f, 0.f, 0.f);
            nf2 = 0.f; cur = cj; seg = 1;
        }
#pragma unroll
        for (int k = 0; k < 8; k++) {
            float4 v = buf[b][k];
            acc[k].x += v.x * inv; acc[k].y += v.y * inv;
            acc[k].z += v.z * inv; acc[k].w += v.w * inv;
        }
        nf2 += ss * inv * inv;
        b ^= 1;
    }
    // final flush
    float* dst = g_part + (size_t)(g * 2 + seg) * ND;
#pragma unroll
    for (int k = 0; k < 8; k++) ((float4*)dst)[k * 32 + lane] = acc[k];
    if (lane == 0) g_pnf2[g * 2 + seg] = nf2;
}

// ---- K5: combine segments -> S_c, ||S_c||^2, base; sort member ranks ----
__global__ __launch_bounds__(256) void k_comb() {
    int c = blockIdx.x, t = threadIdx.x;
    int n = g_cnt[c];
    if (n == 0) return;
    int off = g_off[c];
    int k0 = off / CH, k1 = (off + n - 1) / CH;

    float4 s = make_float4(0.f, 0.f, 0.f, 0.f);
    for (int k = k0; k <= k1; k++) {
        int slot = k * 2 + ((k * CH >= off) ? 0 : 1);
        float4 p = ((const float4*)(g_part + (size_t)slot * ND))[t];
        s.x += p.x; s.y += p.y; s.z += p.z; s.w += p.w;
    }
    ((float4*)(g_sums + (size_t)c * ND))[t] = s;

    float sq = s.x * s.x + s.y * s.y + s.z * s.z + s.w * s.w;
#pragma unroll
    for (int o = 16; o; o >>= 1) sq += __shfl_xor_sync(0xFFFFFFFFu, sq, o);
    __shared__ float sred[8];
    int lane = t & 31, w = t >> 5;
    if (lane == 0) sred[w] = sq;

    // rank members by ascending global index
    __shared__ int sm_m[PAD];
    for (int j = t; j < n; j += 256) sm_m[j] = g_flat[off + j];
    __syncthreads();
    for (int j = t; j < n; j += 256) {
        int mj = sm_m[j];
        int rank = 0;
        for (int u = 0; u < n; u++) rank += (sm_m[u] < mj);
        g_sorted[off + rank] = mj;
    }

    if (t == 0) {
        float s2 = 0.f;
#pragma unroll
        for (int u = 0; u < 8; u++) s2 += sred[u];
        g_s2[c] = s2;
        double nf2 = 0.0;
        for (int k = k0; k <= k1; k++)
            nf2 += (double)g_pnf2[k * 2 + ((k * CH >= off) ? 0 : 1)];
        if (n > 1) {
            double base = (nf2 - (double)s2 / (double)n) / (double)ND;
            atomicAdd(&g_accum, base);
        }
    }
}

// ---- K6: warp-per-sample exclusion correction (only i < n_c fire) ----
__global__ __launch_bounds__(128) void k_corr(const float* __restrict__ x,
                                              const int* __restrict__ lab) {
    int i = blockIdx.x * 4 + (threadIdx.x >> 5);   // 0..511
    int lane = threadIdx.x & 31;
    int c = lab[i];
    int n = g_cnt[c];
    if (i >= n || n <= 1) return;
    int k = g_sorted[g_off[c] + i];

    const float4* xi = (const float4*)x + (size_t)i * 256;
    const float4* xk = (const float4*)x + (size_t)k * 256;
    const float4* sc = (const float4*)g_sums + (size_t)c * 256;
    float a_ii = 0.f, a_ik = 0.f, a_kk = 0.f, a_is = 0.f, a_ks = 0.f;
#pragma unroll
    for (int q = 0; q < 8; q++) {
        float4 vi = xi[q * 32 + lane];
        float4 vk = xk[q * 32 + lane];
        float4 vs = sc[q * 32 + lane];
        a_ii += vi.x * vi.x + vi.y * vi.y + vi.z * vi.z + vi.w * vi.w;
        a_ik += vi.x * vk.x + vi.y * vk.y + vi.z * vk.z + vi.w * vk.w;
        a_kk += vk.x * vk.x + vk.y * vk.y + vk.z * vk.z + vk.w * vk.w;
        a_is += vi.x * vs.x + vi.y * vs.y + vi.z * vs.z + vi.w * vs.w;
        a_ks += vk.x * vs.x + vk.y * vs.y + vk.z * vs.z + vk.w * vs.w;
    }
#pragma unroll
    for (int o = 16; o; o >>= 1) {
        a_ii += __shfl_xor_sync(0xFFFFFFFFu, a_ii, o);
        a_ik += __shfl_xor_sync(0xFFFFFFFFu, a_ik, o);
        a_kk += __shfl_xor_sync(0xFFFFFFFFu, a_kk, o);
        a_is += __shfl_xor_sync(0xFFFFFFFFu, a_is, o);
        a_ks += __shfl_xor_sync(0xFFFFFFFFu, a_ks, o);
    }
    if (lane == 0) {
        float inv_i = 1.0f / fmaxf(sqrtf(a_ii), EPSN);
        float inv_k = 1.0f / fmaxf(sqrtf(a_kk), EPSN);
        float s2 = g_s2[c];
        double nf2_i = (double)a_ii * inv_i * inv_i;
        double fiS   = (double)a_is * inv_i;
        double fifk  = (double)a_ik * inv_i * inv_k;
        double fkS   = (double)a_ks * inv_k;
        double nf2_k = (double)a_kk * inv_k * inv_k;
        double dn = (double)n;
        double base = (nf2_i - 2.0 * fiS / dn + (double)s2 / (dn * dn)) / (double)ND;
        double m = dn - 1.0;
        double fic  = (fiS - fifk) / m;
        double c2   = ((double)s2 - 2.0 * fkS + nf2_k) / (m * m);
        double excl = (nf2_i - 2.0 * fic + c2) / (double)ND;
        atomicAdd(&g_accum, excl - base);
    }
}

// ---- K7: finalize + restore zero-invariants ----
__global__ void k_final(float* out) {
    int t = threadIdx.x;
    if (t == 0) {
        out[0] = (float)(LOSS_WEIGHT * g_accum / (double)NB);
        g_accum = 0.0;
    }
    if (t < NC) g_cnt[t] = 0;
}

extern "C" void kernel_launch(void* const* d_in, const int* in_sizes, int n_in,
                              void* d_out, int out_size) {
    const float* x   = (const float*)d_in[0];
    const int*   lab = (const int*)d_in[1];
    float* out = (float*)d_out;
    (void)in_sizes; (void)n_in; (void)out_size;

    k_hist<<<NB / 1024, 1024>>>(lab);      // launch 1
    k_prefix<<<1, NC>>>();                 // launch 2
    k_scatter<<<NB / 1024, 1024>>>(lab);   // launch 3
    k_fused<<<(NCHUNK + 3) / 4, 128>>>(x, lab);  // launch 4 -> profiled
    k_comb<<<NC, 256>>>();                 // launch 5
    k_corr<<<128, 128>>>(x, lab);          // launch 6
    k_final<<<1, 256>>>(out);              // launch 7
}

// round 7
// speedup vs baseline: 1.1295x; 1.0360x over previous
#include <cuda_runtime.h>
#include <math.h>

#define NB 32768
#define ND 1024
#define NC 256
#define PAD 1024
#define CH 14
#define NCHUNK ((NB + CH - 1) / CH)   // 2341
#define DEPTH 3
#define LOSS_WEIGHT 0.0005
#define EPSN 1e-12f

// ---- static scratch (zero at load; invariants restored in-pipeline) ----
__device__ int    g_cnt[NC];                 // 0 at entry
__device__ int    g_off[NC];
__device__ int    g_cursor[NC];
__device__ int    g_flat[NB];
__device__ int    g_sorted[NB];
__device__ float  g_part[(NCHUNK + 1) * 2 * ND];
__device__ float  g_pnf2[(NCHUNK + 1) * 2];
__device__ float  g_sums[NC * ND];
__device__ float  g_s2[NC];
__device__ double g_accum;                   // 0 at entry
__device__ int    g_done1;                   // 0 at entry
__device__ int    g_done2;                   // 0 at entry

// ---- K1: histogram; last block computes prefix + zeroes cursors ----
__global__ __launch_bounds__(1024) void k_hist(const int* __restrict__ lab) {
    __shared__ int scnt[NC];
    int t = threadIdx.x;
    if (t < NC) scnt[t] = 0;
    __syncthreads();
    atomicAdd(&scnt[lab[blockIdx.x * 1024 + t]], 1);
    __syncthreads();
    if (t < NC && scnt[t]) atomicAdd(&g_cnt[t], scnt[t]);
    __threadfence();
    __shared__ int islast;
    if (t == 0) islast = (atomicAdd(&g_done1, 1) == (int)gridDim.x - 1);
    __syncthreads();
    if (!islast) return;
    // prefix scan over g_cnt (threads 0..255 active, all sync)
    __shared__ int s[NC];
    int v = 0;
    if (t < NC) { v = g_cnt[t]; s[t] = v; }
    __syncthreads();
    for (int o = 1; o < NC; o <<= 1) {
        int add = (t < NC && t >= o) ? s[t - o] : 0;
        __syncthreads();
        if (t < NC) s[t] += add;
        __syncthreads();
    }
    if (t < NC) { g_off[t] = s[t] - v; g_cursor[t] = 0; }
    if (t == 0) g_done1 = 0;
}

// ---- K2: block-aggregated scatter into flat class-sorted list ----
__global__ __launch_bounds__(1024) void k_scatter(const int* __restrict__ lab) {
    __shared__ int scnt[NC];
    __shared__ int sbase[NC];
    int t = threadIdx.x;
    if (t < NC) scnt[t] = 0;
    __syncthreads();
    int row = blockIdx.x * 1024 + t;
    int c = lab[row];
    int r = atomicAdd(&scnt[c], 1);
    __syncthreads();
    if (t < NC && scnt[t]) sbase[t] = atomicAdd(&g_cursor[t], scnt[t]);
    __syncthreads();
    g_flat[g_off[c] + sbase[c] + r] = row;
}

// ---- K3: fused norms + segment partial sums; warp = 14 rows, cp.async depth-3 ----
__global__ __launch_bounds__(128, 4) void k_fused(const float* __restrict__ x,
                                                  const int* __restrict__ lab) {
    __shared__ float4 ring[4][DEPTH][256];   // 48KB
    int t = threadIdx.x, lane = t & 31, w = t >> 5;
    int g = blockIdx.x * 4 + w;
    int r0 = g * CH;
    int cnt = 0;
    if (r0 < NB) { cnt = NB - r0; if (cnt > CH) cnt = CH; }

    int idx = 0, cl = -1;
    if (lane < cnt) { idx = g_flat[r0 + lane]; cl = lab[idx]; }

    const float4* xb = (const float4*)x;
    unsigned smem_base = (unsigned)__cvta_generic_to_shared(&ring[w][0][lane]);

    // prologue: issue DEPTH stages (empty commit groups beyond cnt)
#pragma unroll
    for (int s = 0; s < DEPTH; s++) {
        if (s < cnt) {
            int is = __shfl_sync(0xFFFFFFFFu, idx, s);
            const float4* src = xb + (size_t)is * 256 + lane;
            unsigned d = smem_base + s * 4096;
#pragma unroll
            for (int k = 0; k < 8; k++)
                asm volatile("cp.async.cg.shared.global [%0], [%1], 16;"
                             :: "r"(d + k * 512), "l"(src + k * 32));
        }
        asm volatile("cp.async.commit_group;");
    }

    float4 acc[8];
#pragma unroll
    for (int k = 0; k < 8; k++) acc[k] = make_float4(0.f, 0.f, 0.f, 0.f);
    float nf2 = 0.f;
    int cur = __shfl_sync(0xFFFFFFFFu, cl, 0);
    int seg = 0, st = 0;

    for (int j = 0; j < cnt; j++) {
        asm volatile("cp.async.wait_group %0;" :: "n"(DEPTH - 1));
        float4 v[8];
#pragma unroll
        for (int k = 0; k < 8; k++) v[k] = ring[w][st][k * 32 + lane];

        float ss = 0.f;
#pragma unroll
        for (int k = 0; k < 8; k++)
            ss += v[k].x * v[k].x + v[k].y * v[k].y + v[k].z * v[k].z + v[k].w * v[k].w;
#pragma unroll
        for (int o = 16; o; o >>= 1) ss += __shfl_xor_sync(0xFFFFFFFFu, ss, o);
        float inv = 1.0f / fmaxf(sqrtf(ss), EPSN);

        int cj = __shfl_sync(0xFFFFFFFFu, cl, j);
        if (cj != cur) {                     // class boundary: flush segment 0
            float* dst = g_part + (size_t)(g * 2 + seg) * ND;
#pragma unroll
            for (int k = 0; k < 8; k++) ((float4*)dst)[k * 32 + lane] = acc[k];
            if (lane == 0) g_pnf2[g * 2 + seg] = nf2;
#pragma unroll
            for (int k = 0; k < 8; k++) acc[k] = make_float4(0.f, 0.f, 0.f, 0.f);
            nf2 = 0.f; cur = cj; seg = 1;
        }
#pragma unroll
        for (int k = 0; k < 8; k++) {
            acc[k].x += v[k].x * inv; acc[k].y += v[k].y * inv;
            acc[k].z += v[k].z * inv; acc[k].w += v[k].w * inv;
        }
        nf2 += ss * inv * inv;

        // issue stage j+DEPTH into the slot just freed
        int jn = j + DEPTH;
        if (jn < cnt) {
            int in = __shfl_sync(0xFFFFFFFFu, idx, jn);
            const float4* src = xb + (size_t)in * 256 + lane;
            unsigned d = smem_base + st * 4096;
#pragma unroll
            for (int k = 0; k < 8; k++)
                asm volatile("cp.async.cg.shared.global [%0], [%1], 16;"
                             :: "r"(d + k * 512), "l"(src + k * 32));
        }
        asm volatile("cp.async.commit_group;");
        st = (st + 1 == DEPTH) ? 0 : st + 1;
    }
    if (cnt > 0) {
        float* dst = g_part + (size_t)(g * 2 + seg) * ND;
#pragma unroll
        for (int k = 0; k < 8; k++) ((float4*)dst)[k * 32 + lane] = acc[k];
        if (lane == 0) g_pnf2[g * 2 + seg] = nf2;
    }
}

// ---- K4: combine segments -> S_c, ||S_c||^2, base; sort member ranks ----
__global__ __launch_bounds__(256) void k_comb() {
    int c = blockIdx.x, t = threadIdx.x;
    int n = g_cnt[c];
    if (n == 0) return;
    int off = g_off[c];
    int k0 = off / CH, k1 = (off + n - 1) / CH;

    float4 s = make_float4(0.f, 0.f, 0.f, 0.f);
    for (int k = k0; k <= k1; k++) {
        int slot = k * 2 + ((k * CH >= off) ? 0 : 1);
        float4 p = ((const float4*)(g_part + (size_t)slot * ND))[t];
        s.x += p.x; s.y += p.y; s.z += p.z; s.w += p.w;
    }
    ((float4*)(g_sums + (size_t)c * ND))[t] = s;

    float sq = s.x * s.x + s.y * s.y + s.z * s.z + s.w * s.w;
#pragma unroll
    for (int o = 16; o; o >>= 1) sq += __shfl_xor_sync(0xFFFFFFFFu, sq, o);
    __shared__ float sred[8];
    int lane = t & 31, w = t >> 5;
    if (lane == 0) sred[w] = sq;

    __shared__ int sm_m[PAD];
    for (int j = t; j < n; j += 256) sm_m[j] = g_flat[off + j];
    __syncthreads();
    for (int j = t; j < n; j += 256) {
        int mj = sm_m[j];
        int rank = 0;
        for (int u = 0; u < n; u++) rank += (sm_m[u] < mj);
        g_sorted[off + rank] = mj;
    }

    if (t == 0) {
        float s2 = 0.f;
#pragma unroll
        for (int u = 0; u < 8; u++) s2 += sred[u];
        g_s2[c] = s2;
        double nf2 = 0.0;
        for (int k = k0; k <= k1; k++)
            nf2 += (double)g_pnf2[k * 2 + ((k * CH >= off) ? 0 : 1)];
        if (n > 1) {
            double base = (nf2 - (double)s2 / (double)n) / (double)ND;
            atomicAdd(&g_accum, base);
        }
    }
}

// ---- K5: exclusion corrections; last block finalizes + restores invariants ----
__global__ __launch_bounds__(128) void k_corr(const float* __restrict__ x,
                                              const int* __restrict__ lab,
                                              float* __restrict__ out) {
    int i = blockIdx.x * 4 + (threadIdx.x >> 5);   // 0..511
    int lane = threadIdx.x & 31;
    int c = lab[i];
    int n = g_cnt[c];
    if (i < n && n > 1) {
        int k = g_sorted[g_off[c] + i];
        const float4* xi = (const float4*)x + (size_t)i * 256;
        const float4* xk = (const float4*)x + (size_t)k * 256;
        const float4* sc = (const float4*)g_sums + (size_t)c * 256;
        float a_ii = 0.f, a_ik = 0.f, a_kk = 0.f, a_is = 0.f, a_ks = 0.f;
#pragma unroll
        for (int q = 0; q < 8; q++) {
            float4 vi = xi[q * 32 + lane];
            float4 vk = xk[q * 32 + lane];
            float4 vs = sc[q * 32 + lane];
            a_ii += vi.x * vi.x + vi.y * vi.y + vi.z * vi.z + vi.w * vi.w;
            a_ik += vi.x * vk.x + vi.y * vk.y + vi.z * vk.z + vi.w * vk.w;
            a_kk += vk.x * vk.x + vk.y * vk.y + vk.z * vk.z + vk.w * vk.w;
            a_is += vi.x * vs.x + vi.y * vs.y + vi.z * vs.z + vi.w * vs.w;
            a_ks += vk.x * vs.x + vk.y * vs.y + vk.z * vs.z + vk.w * vs.w;
        }
#pragma unroll
        for (int o = 16; o; o >>= 1) {
            a_ii += __shfl_xor_sync(0xFFFFFFFFu, a_ii, o);
            a_ik += __shfl_xor_sync(0xFFFFFFFFu, a_ik, o);
            a_kk += __shfl_xor_sync(0xFFFFFFFFu, a_kk, o);
            a_is += __shfl_xor_sync(0xFFFFFFFFu, a_is, o);
            a_ks += __shfl_xor_sync(0xFFFFFFFFu, a_ks, o);
        }
        if (lane == 0) {
            float inv_i = 1.0f / fmaxf(sqrtf(a_ii), EPSN);
            float inv_k = 1.0f / fmaxf(sqrtf(a_kk), EPSN);
            float s2 = g_s2[c];
            double nf2_i = (double)a_ii * inv_i * inv_i;
            double fiS   = (double)a_is * inv_i;
            double fifk  = (double)a_ik * inv_i * inv_k;
            double fkS   = (double)a_ks * inv_k;
            double nf2_k = (double)a_kk * inv_k * inv_k;
            double dn = (double)n;
            double base = (nf2_i - 2.0 * fiS / dn + (double)s2 / (dn * dn)) / (double)ND;
            double m = dn - 1.0;
            double fic  = (fiS - fifk) / m;
            double c2   = ((double)s2 - 2.0 * fkS + nf2_k) / (m * m);
            double excl = (nf2_i - 2.0 * fic + c2) / (double)ND;
            atomicAdd(&g_accum, excl - base);
        }
    }
    __threadfence();
    __syncthreads();
    __shared__ int islast;
    if (threadIdx.x == 0) islast = (atomicAdd(&g_done2, 1) == (int)gridDim.x - 1);
    __syncthreads();
    if (islast) {
        if (threadIdx.x == 0) {
            out[0] = (float)(LOSS_WEIGHT * g_accum / (double)NB);
            g_accum = 0.0;
            g_done2 = 0;
        }
        for (int u = threadIdx.x; u < NC; u += 128) g_cnt[u] = 0;
    }
}

extern "C" void kernel_launch(void* const* d_in, const int* in_sizes, int n_in,
                              void* d_out, int out_size) {
    const float* x   = (const float*)d_in[0];
    const int*   lab = (const int*)d_in[1];
    float* out = (float*)d_out;
    (void)in_sizes; (void)n_in; (void)out_size;

    k_hist<<<NB / 1024, 1024>>>(lab);
    k_scatter<<<NB / 1024, 1024>>>(lab);
    k_fused<<<(NCHUNK + 3) / 4, 128>>>(x, lab);
    k_comb<<<NC, 256>>>();
    k_corr<<<128, 128>>>(x, lab, out);
}

// round 8
// speedup vs baseline: 1.3652x; 1.2087x over previous
#include <cuda_runtime.h>
#include <math.h>

#define NB 32768
#define ND 1024
#define NC 256
#define PAD 1024
#define CH 14
#define NCHUNK ((NB + CH - 1) / CH)   // 2341
#define DEPTH 3
#define LOSS_WEIGHT 0.0005
#define EPSN 1e-12f

// ---- static scratch (zero at load; invariants restored in-pipeline) ----
__device__ int    g_cnt[NC];                 // 0 at entry
__device__ int    g_off[NC];
__device__ int    g_cursor[NC];
__device__ int    g_flat[NB];
__device__ int    g_sorted[NB];
__device__ float  g_sums[NC * ND];           // S_c, accumulated via REDG
__device__ float  g_nf2[NC];                 // sum ||f||^2 per class
__device__ float  g_s2[NC];
__device__ double g_accum;                   // 0 at entry
__device__ int    g_done1;                   // 0 at entry
__device__ int    g_done2;                   // 0 at entry

// ---- K0: zero accumulators (also shifts k_fused into profiled slot 4) ----
__global__ __launch_bounds__(1024) void k_pre() {
    int t = blockIdx.x * 1024 + threadIdx.x;        // 32768 threads
    ((float4*)g_sums)[t * 2] = make_float4(0.f, 0.f, 0.f, 0.f);
    ((float4*)g_sums)[t * 2 + 1] = make_float4(0.f, 0.f, 0.f, 0.f);
    if (t < NC) g_nf2[t] = 0.f;
}

// ---- K1: histogram; last block computes prefix + zeroes cursors ----
__global__ __launch_bounds__(1024) void k_hist(const int* __restrict__ lab) {
    __shared__ int scnt[NC];
    int t = threadIdx.x;
    if (t < NC) scnt[t] = 0;
    __syncthreads();
    atomicAdd(&scnt[lab[blockIdx.x * 1024 + t]], 1);
    __syncthreads();
    if (t < NC && scnt[t]) atomicAdd(&g_cnt[t], scnt[t]);
    __threadfence();
    __shared__ int islast;
    if (t == 0) islast = (atomicAdd(&g_done1, 1) == (int)gridDim.x - 1);
    __syncthreads();
    if (!islast) return;
    __shared__ int s[NC];
    int v = 0;
    if (t < NC) { v = g_cnt[t]; s[t] = v; }
    __syncthreads();
    for (int o = 1; o < NC; o <<= 1) {
        int add = (t < NC && t >= o) ? s[t - o] : 0;
        __syncthreads();
        if (t < NC) s[t] += add;
        __syncthreads();
    }
    if (t < NC) { g_off[t] = s[t] - v; g_cursor[t] = 0; }
    if (t == 0) g_done1 = 0;
}

// ---- K2: block-aggregated scatter into flat class-sorted list ----
__global__ __launch_bounds__(1024) void k_scatter(const int* __restrict__ lab) {
    __shared__ int scnt[NC];
    __shared__ int sbase[NC];
    int t = threadIdx.x;
    if (t < NC) scnt[t] = 0;
    __syncthreads();
    int row = blockIdx.x * 1024 + t;
    int c = lab[row];
    int r = atomicAdd(&scnt[c], 1);
    __syncthreads();
    if (t < NC && scnt[t]) sbase[t] = atomicAdd(&g_cursor[t], scnt[t]);
    __syncthreads();
    g_flat[g_off[c] + sbase[c] + r] = row;
}

// ---- K3 (profiled slot 4): fused norms + atomic class sums; warp = 14 rows ----
__global__ __launch_bounds__(128, 4) void k_fused(const float* __restrict__ x,
                                                  const int* __restrict__ lab) {
    __shared__ float4 ring[4][DEPTH][256];   // 48KB
    int t = threadIdx.x, lane = t & 31, w = t >> 5;
    int g = blockIdx.x * 4 + w;
    int r0 = g * CH;
    int cnt = 0;
    if (r0 < NB) { cnt = NB - r0; if (cnt > CH) cnt = CH; }

    int idx = 0, cl = -1;
    if (lane < cnt) { idx = g_flat[r0 + lane]; cl = lab[idx]; }

    const float4* xb = (const float4*)x;
    unsigned smem_base = (unsigned)__cvta_generic_to_shared(&ring[w][0][lane]);

#pragma unroll
    for (int s = 0; s < DEPTH; s++) {
        if (s < cnt) {
            int is = __shfl_sync(0xFFFFFFFFu, idx, s);
            const float4* src = xb + (size_t)is * 256 + lane;
            unsigned d = smem_base + s * 4096;
#pragma unroll
            for (int k = 0; k < 8; k++)
                asm volatile("cp.async.cg.shared.global [%0], [%1], 16;"
                             :: "r"(d + k * 512), "l"(src + k * 32));
        }
        asm volatile("cp.async.commit_group;");
    }

    float4 acc[8];
#pragma unroll
    for (int k = 0; k < 8; k++) acc[k] = make_float4(0.f, 0.f, 0.f, 0.f);
    float nf2 = 0.f;
    int cur = __shfl_sync(0xFFFFFFFFu, cl, 0);
    int st = 0;

    for (int j = 0; j < cnt; j++) {
        asm volatile("cp.async.wait_group %0;" :: "n"(DEPTH - 1));
        float4 v[8];
#pragma unroll
        for (int k = 0; k < 8; k++) v[k] = ring[w][st][k * 32 + lane];

        float ss = 0.f;
#pragma unroll
        for (int k = 0; k < 8; k++)
            ss += v[k].x * v[k].x + v[k].y * v[k].y + v[k].z * v[k].z + v[k].w * v[k].w;
#pragma unroll
        for (int o = 16; o; o >>= 1) ss += __shfl_xor_sync(0xFFFFFFFFu, ss, o);
        float inv = 1.0f / fmaxf(sqrtf(ss), EPSN);

        int cj = __shfl_sync(0xFFFFFFFFu, cl, j);
        if (cj != cur) {                     // class boundary: flush to atomics
            float* dst = g_sums + (size_t)cur * ND;
#pragma unroll
            for (int k = 0; k < 8; k++) {
                int d0 = k * 128 + lane * 4;
                atomicAdd(&dst[d0 + 0], acc[k].x);
                atomicAdd(&dst[d0 + 1], acc[k].y);
                atomicAdd(&dst[d0 + 2], acc[k].z);
                atomicAdd(&dst[d0 + 3], acc[k].w);
            }
            if (lane == 0) atomicAdd(&g_nf2[cur], nf2);
#pragma unroll
            for (int k = 0; k < 8; k++) acc[k] = make_float4(0.f, 0.f, 0.f, 0.f);
            nf2 = 0.f; cur = cj;
        }
#pragma unroll
        for (int k = 0; k < 8; k++) {
            acc[k].x += v[k].x * inv; acc[k].y += v[k].y * inv;
            acc[k].z += v[k].z * inv; acc[k].w += v[k].w * inv;
        }
        nf2 += ss * inv * inv;

        int jn = j + DEPTH;
        if (jn < cnt) {
            int in = __shfl_sync(0xFFFFFFFFu, idx, jn);
            const float4* src = xb + (size_t)in * 256 + lane;
            unsigned d = smem_base + st * 4096;
#pragma unroll
            for (int k = 0; k < 8; k++)
                asm volatile("cp.async.cg.shared.global [%0], [%1], 16;"
                             :: "r"(d + k * 512), "l"(src + k * 32));
        }
        asm volatile("cp.async.commit_group;");
        st = (st + 1 == DEPTH) ? 0 : st + 1;
    }
    if (cnt > 0) {
        float* dst = g_sums + (size_t)cur * ND;
#pragma unroll
        for (int k = 0; k < 8; k++) {
            int d0 = k * 128 + lane * 4;
            atomicAdd(&dst[d0 + 0], acc[k].x);
            atomicAdd(&dst[d0 + 1], acc[k].y);
            atomicAdd(&dst[d0 + 2], acc[k].z);
            atomicAdd(&dst[d0 + 3], acc[k].w);
        }
        if (lane == 0) atomicAdd(&g_nf2[cur], nf2);
    }
}

// ---- K4: ||S_c||^2 + base contribution; sort member ranks ----
__global__ __launch_bounds__(256) void k_comb() {
    int c = blockIdx.x, t = threadIdx.x;
    int n = g_cnt[c];
    if (n == 0) return;
    int off = g_off[c];

    float4 s = ((const float4*)(g_sums + (size_t)c * ND))[t];
    float sq = s.x * s.x + s.y * s.y + s.z * s.z + s.w * s.w;
#pragma unroll
    for (int o = 16; o; o >>= 1) sq += __shfl_xor_sync(0xFFFFFFFFu, sq, o);
    __shared__ float sred[8];
    int lane = t & 31, w = t >> 5;
    if (lane == 0) sred[w] = sq;

    __shared__ int sm_m[PAD];
    for (int j = t; j < n; j += 256) sm_m[j] = g_flat[off + j];
    __syncthreads();
    for (int j = t; j < n; j += 256) {
        int mj = sm_m[j];
        int rank = 0;
        for (int u = 0; u < n; u++) rank += (sm_m[u] < mj);
        g_sorted[off + rank] = mj;
    }

    if (t == 0) {
        float s2 = 0.f;
#pragma unroll
        for (int u = 0; u < 8; u++) s2 += sred[u];
        g_s2[c] = s2;
        if (n > 1) {
            double base = ((double)g_nf2[c] - (double)s2 / (double)n) / (double)ND;
            atomicAdd(&g_accum, base);
        }
    }
}

// ---- K5: exclusion corrections; last block finalizes + restores invariants ----
__global__ __launch_bounds__(128) void k_corr(const float* __restrict__ x,
                                              const int* __restrict__ lab,
                                              float* __restrict__ out) {
    int i = blockIdx.x * 4 + (threadIdx.x >> 5);   // 0..511
    int lane = threadIdx.x & 31;
    int c = lab[i];
    int n = g_cnt[c];
    if (i < n && n > 1) {
        int k = g_sorted[g_off[c] + i];
        const float4* xi = (const float4*)x + (size_t)i * 256;
        const float4* xk = (const float4*)x + (size_t)k * 256;
        const float4* sc = (const float4*)g_sums + (size_t)c * 256;
        float a_ii = 0.f, a_ik = 0.f, a_kk = 0.f, a_is = 0.f, a_ks = 0.f;
#pragma unroll
        for (int q = 0; q < 8; q++) {
            float4 vi = xi[q * 32 + lane];
            float4 vk = xk[q * 32 + lane];
            float4 vs = sc[q * 32 + lane];
            a_ii += vi.x * vi.x + vi.y * vi.y + vi.z * vi.z + vi.w * vi.w;
            a_ik += vi.x * vk.x + vi.y * vk.y + vi.z * vk.z + vi.w * vk.w;
            a_kk += vk.x * vk.x + vk.y * vk.y + vk.z * vk.z + vk.w * vk.w;
            a_is += vi.x * vs.x + vi.y * vs.y + vi.z * vs.z + vi.w * vs.w;
            a_ks += vk.x * vs.x + vk.y * vs.y + vk.z * vs.z + vk.w * vs.w;
        }
#pragma unroll
        for (int o = 16; o; o >>= 1) {
            a_ii += __shfl_xor_sync(0xFFFFFFFFu, a_ii, o);
            a_ik += __shfl_xor_sync(0xFFFFFFFFu, a_ik, o);
            a_kk += __shfl_xor_sync(0xFFFFFFFFu, a_kk, o);
            a_is += __shfl_xor_sync(0xFFFFFFFFu, a_is, o);
            a_ks += __shfl_xor_sync(0xFFFFFFFFu, a_ks, o);
        }
        if (lane == 0) {
            float inv_i = 1.0f / fmaxf(sqrtf(a_ii), EPSN);
            float inv_k = 1.0f / fmaxf(sqrtf(a_kk), EPSN);
            float s2 = g_s2[c];
            double nf2_i = (double)a_ii * inv_i * inv_i;
            double fiS   = (double)a_is * inv_i;
            double fifk  = (double)a_ik * inv_i * inv_k;
            double fkS   = (double)a_ks * inv_k;
            double nf2_k = (double)a_kk * inv_k * inv_k;
            double dn = (double)n;
            double base = (nf2_i - 2.0 * fiS / dn + (double)s2 / (dn * dn)) / (double)ND;
            double m = dn - 1.0;
            double fic  = (fiS - fifk) / m;
            double c2   = ((double)s2 - 2.0 * fkS + nf2_k) / (m * m);
            double excl = (nf2_i - 2.0 * fic + c2) / (double)ND;
            atomicAdd(&g_accum, excl - base);
        }
    }
    __threadfence();
    __syncthreads();
    __shared__ int islast;
    if (threadIdx.x == 0) islast = (atomicAdd(&g_done2, 1) == (int)gridDim.x - 1);
    __syncthreads();
    if (islast) {
        if (threadIdx.x == 0) {
            out[0] = (float)(LOSS_WEIGHT * g_accum / (double)NB);
            g_accum = 0.0;
            g_done2 = 0;
        }
        for (int u = threadIdx.x; u < NC; u += 128) g_cnt[u] = 0;
    }
}

extern "C" void kernel_launch(void* const* d_in, const int* in_sizes, int n_in,
                              void* d_out, int out_size) {
    const float* x   = (const float*)d_in[0];
    const int*   lab = (const int*)d_in[1];
    float* out = (float*)d_out;
    (void)in_sizes; (void)n_in; (void)out_size;

    k_pre<<<32, 1024>>>();                       // 1
    k_hist<<<NB / 1024, 1024>>>(lab);            // 2
    k_scatter<<<NB / 1024, 1024>>>(lab);         // 3
    k_fused<<<(NCHUNK + 3) / 4, 128>>>(x, lab);  // 4 -> profiled
    k_comb<<<NC, 256>>>();                       // 5
    k_corr<<<128, 128>>>(x, lab, out);           // 6
}